// round 5
// baseline (speedup 1.0000x reference)
#include <cuda_runtime.h>
#include <cstdint>

#define HID 64
#define H2  128
#define NSEG 64
#define CH 1024
#define MAXN 50048
#define MAXT 1600512
#define MAXCHUNKS 1600
#define SCAP 27648   // per-seg smem capacity (words) = 110592 B

// ---------------- device scratch ----------------
__device__ float g_P[MAXN * H2];                 // 25.6 MB  h @ W1[:64,:]
__device__ unsigned long long g_pack[MAXT];      // src | dst<<16 | conn<<32 | seg<<33
__device__ unsigned g_ulog[MAXT];                // order-preserving uint32 logits
__device__ int g_histT[NSEG * MAXCHUNKS];        // [seg][chunk] all-edge counts
__device__ int g_histPT[NSEG * MAXCHUNKS];       // [seg][chunk] pos-edge counts
__device__ int g_posCnt[NSEG];
__device__ int g_segCnt[NSEG];
__device__ int g_segStart[NSEG];
__device__ unsigned g_thr[NSEG];

__device__ __forceinline__ float unflip(unsigned u) {
    unsigned fb = (u & 0x80000000u) ? (u ^ 0x80000000u) : ~u;
    return __uint_as_float(fb);
}

// ---------------- hist (+ zero node-mask; no pre-zeroed globals needed) ----------------
__global__ __launch_bounds__(256) void k_hist(const int* __restrict__ pos,
                                              const int* __restrict__ neg,
                                              const int* __restrict__ nb,
                                              float* __restrict__ outNM,
                                              int E, int T, int N) {
    __shared__ int sh[NSEG];
    __shared__ int shp[NSEG];
    int tid = threadIdx.x;
    if (tid < NSEG) { sh[tid] = 0; shp[tid] = 0; }
    __syncthreads();
    int base = blockIdx.x * CH;
    for (int i = tid; i < CH; i += 256) {
        int e = base + i;
        if (e < T) {
            int src = (e < E) ? pos[e] : neg[e - E];
            int s = nb[src];
            atomicAdd(&sh[s], 1);
            if (e < E) atomicAdd(&shp[s], 1);
        }
    }
    int g = blockIdx.x * 256 + tid;
    if (g < N) outNM[g] = 0.0f;
    __syncthreads();
    if (tid < NSEG) {
        g_histT[tid * MAXCHUNKS + blockIdx.x] = sh[tid];
        g_histPT[tid * MAXCHUNKS + blockIdx.x] = shp[tid];
    }
}

// ---------------- scanC: seg starts/counts/posCnt + per-chunk prefix ----------------
__global__ __launch_bounds__(256) void k_scanC(int nc) {
    __shared__ int red[256];
    __shared__ int sh[256];
    __shared__ int s_start;
    int s = blockIdx.x;
    int tid = threadIdx.x;
    // start = total count of segs < s
    int acc = 0;
    for (int r = 0; r < s; r++)
        for (int c = tid; c < nc; c += 256) acc += g_histT[r * MAXCHUNKS + c];
    red[tid] = acc;
    __syncthreads();
    for (int off = 128; off; off >>= 1) {
        if (tid < off) red[tid] += red[tid + off];
        __syncthreads();
    }
    if (tid == 0) { s_start = red[0]; g_segStart[s] = red[0]; }
    __syncthreads();
    // posCnt for this seg
    int accP = 0;
    for (int c = tid; c < nc; c += 256) accP += g_histPT[s * MAXCHUNKS + c];
    red[tid] = accP;
    __syncthreads();
    for (int off = 128; off; off >>= 1) {
        if (tid < off) red[tid] += red[tid + off];
        __syncthreads();
    }
    if (tid == 0) g_posCnt[s] = red[0];
    // per-chunk exclusive prefix within this seg (contiguous row)
    int q = (nc + 255) / 256;
    int c0 = tid * q;
    int c1 = min(nc, c0 + q);
    int mySum = 0;
    for (int c = c0; c < c1; c++) mySum += g_histT[s * MAXCHUNKS + c];
    sh[tid] = mySum;
    __syncthreads();
    for (int off = 1; off < 256; off <<= 1) {
        int v = (tid >= off) ? sh[tid - off] : 0;
        __syncthreads();
        sh[tid] += v;
        __syncthreads();
    }
    if (tid == 255) g_segCnt[s] = sh[255];
    int off = s_start + sh[tid] - mySum;
    for (int c = c0; c < c1; c++) {
        int v = g_histT[s * MAXCHUNKS + c];
        g_histT[s * MAXCHUNKS + c] = off;
        off += v;
    }
}

// ---------------- scatter + fused gemm P = h @ W1[:64,:] ----------------
__global__ __launch_bounds__(256) void k_scatG(const int* __restrict__ pos,
                                               const int* __restrict__ neg,
                                               const int* __restrict__ nb,
                                               const float* __restrict__ h,
                                               const float* __restrict__ W1,
                                               int E, int T, int N) {
    __shared__ float Ws[HID][H2];
    __shared__ int cnt[NSEG];
    __shared__ int wcnt[8][NSEG];
    int tid = threadIdx.x, w = tid >> 5, lane = tid & 31;
    int chunk = blockIdx.x;

    // ---- phase A: gemm (grid-stride over 64-node blocks) ----
    for (int i = tid; i < HID * H2; i += 256) Ws[i / H2][i % H2] = W1[i];
    __syncthreads();
    {
        int j = lane * 4;
        int totalWarps = gridDim.x * 8;
        for (int n0 = (blockIdx.x * 8 + w) * 8; n0 < N; n0 += totalWarps * 8) {
            float h0[8], h1[8];
#pragma unroll
            for (int m = 0; m < 8; m++) {
                int nm = n0 + m;
                if (nm < N) { h0[m] = h[nm * HID + lane]; h1[m] = h[nm * HID + 32 + lane]; }
                else { h0[m] = 0.f; h1[m] = 0.f; }
            }
            float4 acc[8];
#pragma unroll
            for (int m = 0; m < 8; m++) acc[m] = make_float4(0.f, 0.f, 0.f, 0.f);
#pragma unroll
            for (int k = 0; k < 64; k++) {
                float4 wv = *(const float4*)&Ws[k][j];
#pragma unroll
                for (int m = 0; m < 8; m++) {
                    float hv = __shfl_sync(0xffffffffu, (k < 32) ? h0[m] : h1[m], k & 31);
                    acc[m].x += hv * wv.x; acc[m].y += hv * wv.y;
                    acc[m].z += hv * wv.z; acc[m].w += hv * wv.w;
                }
            }
#pragma unroll
            for (int m = 0; m < 8; m++)
                if (n0 + m < N) *(float4*)&g_P[(n0 + m) * H2 + j] = acc[m];
        }
    }

    // ---- phase B: stable counting-sort scatter ----
    if (tid < NSEG) cnt[tid] = g_histT[tid * MAXCHUNKS + chunk];
#pragma unroll
    for (int r = 0; r < CH / 256; r++) {
        int e = chunk * CH + r * 256 + tid;
        bool valid = e < T;
        int seg = 0;
        unsigned long long pk = 0;
        if (valid) {
            int src, dst;
            if (e < E) { src = pos[e]; dst = pos[E + e]; }
            else       { src = neg[e - E]; dst = neg[E + (e - E)]; }
            seg = nb[src];
            pk = (unsigned long long)(unsigned)src
               | ((unsigned long long)(unsigned)dst << 16)
               | ((unsigned long long)(e < E ? 1u : 0u) << 32)
               | ((unsigned long long)(unsigned)seg << 33);
        }
        for (int i = tid; i < 8 * NSEG; i += 256) ((int*)wcnt)[i] = 0;
        __syncthreads();
        unsigned m = __match_any_sync(0xffffffffu, valid ? seg : (256 + lane));
        int rank = __popc(m & ((1u << lane) - 1u));
        if (valid && rank == 0) wcnt[w][seg] = __popc(m);
        __syncthreads();
        if (tid < NSEG) {
            int acc = cnt[tid];
#pragma unroll
            for (int ww = 0; ww < 8; ww++) {
                int v = wcnt[ww][tid];
                wcnt[ww][tid] = acc;
                acc += v;
            }
            cnt[tid] = acc;
        }
        __syncthreads();
        if (valid) g_pack[wcnt[w][seg] + rank] = pk;
        __syncthreads();
    }
}

// ---------------- MLP: mod-148 SM-affine tiles, 2 edges per half-warp ----------------
__global__ __launch_bounds__(256) void k_mlp(const float* __restrict__ W1,
                                             const float* __restrict__ b1,
                                             const float* __restrict__ lng,
                                             const float* __restrict__ lnb,
                                             const float* __restrict__ W2,
                                             const float* __restrict__ b2,
                                             int T, int MT) {
    int bid = blockIdx.x;
    int tile = (bid % 148) * 3 + bid / 148;
    int start = tile * MT;
    if (start >= T) return;
    int end = min(T, start + MT);
    int lane = threadIdx.x & 31;
    int half = lane >> 4, hl = lane & 15;
    int w = threadIdx.x >> 5;
    int j = hl * 8;
    float4 wL0 = *(const float4*)&W1[64 * H2 + j];
    float4 wL1 = *(const float4*)&W1[64 * H2 + j + 4];
    float4 bb0 = *(const float4*)&b1[j];
    float4 bb1 = *(const float4*)&b1[j + 4];
    float4 g0 = *(const float4*)&lng[j];
    float4 g1 = *(const float4*)&lng[j + 4];
    float4 e0 = *(const float4*)&lnb[j];
    float4 e1 = *(const float4*)&lnb[j + 4];
    float4 w20 = *(const float4*)&W2[j];
    float4 w21 = *(const float4*)&W2[j + 4];
    float b2v = b2[0];
    for (int t2 = start + w * 4; t2 < end; t2 += 32) {
        int ta = t2 + half;
        int tb = t2 + 2 + half;
        unsigned long long pa = (ta < T) ? g_pack[ta] : 0ull;
        unsigned long long pb = (tb < T) ? g_pack[tb] : 0ull;
        int sa = (int)(pa & 0xffffull), da = (int)((pa >> 16) & 0xffffull);
        int sb = (int)(pb & 0xffffull), db = (int)((pb >> 16) & 0xffffull);
        float ca = (float)((pa >> 32) & 1ull);
        float cb = (float)((pb >> 32) & 1ull);
        const float4* psa = (const float4*)&g_P[sa * H2 + j];
        const float4* pda = (const float4*)&g_P[da * H2 + j];
        const float4* psb = (const float4*)&g_P[sb * H2 + j];
        const float4* pdb = (const float4*)&g_P[db * H2 + j];
        float4 Aa0 = psa[0], Aa1 = psa[1], Ca0 = pda[0], Ca1 = pda[1];
        float4 Ab0 = psb[0], Ab1 = psb[1], Cb0 = pdb[0], Cb1 = pdb[1];
        // edge A
        float xa0 = Aa0.x + Ca0.x + ca * wL0.x + bb0.x;
        float xa1 = Aa0.y + Ca0.y + ca * wL0.y + bb0.y;
        float xa2 = Aa0.z + Ca0.z + ca * wL0.z + bb0.z;
        float xa3 = Aa0.w + Ca0.w + ca * wL0.w + bb0.w;
        float xa4 = Aa1.x + Ca1.x + ca * wL1.x + bb1.x;
        float xa5 = Aa1.y + Ca1.y + ca * wL1.y + bb1.y;
        float xa6 = Aa1.z + Ca1.z + ca * wL1.z + bb1.z;
        float xa7 = Aa1.w + Ca1.w + ca * wL1.w + bb1.w;
        // edge B
        float xb0 = Ab0.x + Cb0.x + cb * wL0.x + bb0.x;
        float xb1 = Ab0.y + Cb0.y + cb * wL0.y + bb0.y;
        float xb2 = Ab0.z + Cb0.z + cb * wL0.z + bb0.z;
        float xb3 = Ab0.w + Cb0.w + cb * wL0.w + bb0.w;
        float xb4 = Ab1.x + Cb1.x + cb * wL1.x + bb1.x;
        float xb5 = Ab1.y + Cb1.y + cb * wL1.y + bb1.y;
        float xb6 = Ab1.z + Cb1.z + cb * wL1.z + bb1.z;
        float xb7 = Ab1.w + Cb1.w + cb * wL1.w + bb1.w;
        float sA = xa0+xa1+xa2+xa3+xa4+xa5+xa6+xa7;
        float qA = xa0*xa0+xa1*xa1+xa2*xa2+xa3*xa3+xa4*xa4+xa5*xa5+xa6*xa6+xa7*xa7;
        float sB = xb0+xb1+xb2+xb3+xb4+xb5+xb6+xb7;
        float qB = xb0*xb0+xb1*xb1+xb2*xb2+xb3*xb3+xb4*xb4+xb5*xb5+xb6*xb6+xb7*xb7;
#pragma unroll
        for (int o = 8; o; o >>= 1) {
            sA += __shfl_xor_sync(0xffffffffu, sA, o);
            qA += __shfl_xor_sync(0xffffffffu, qA, o);
            sB += __shfl_xor_sync(0xffffffffu, sB, o);
            qB += __shfl_xor_sync(0xffffffffu, qB, o);
        }
        float muA = sA * (1.0f / 128.0f);
        float varA = qA * (1.0f / 128.0f) - muA * muA;
        float rsA = rsqrtf(varA + 1e-5f);
        float muB = sB * (1.0f / 128.0f);
        float varB = qB * (1.0f / 128.0f) - muB * muB;
        float rsB = rsqrtf(varB + 1e-5f);
        float pA =
          fmaxf((xa0 - muA) * rsA * g0.x + e0.x, 0.0f) * w20.x
        + fmaxf((xa1 - muA) * rsA * g0.y + e0.y, 0.0f) * w20.y
        + fmaxf((xa2 - muA) * rsA * g0.z + e0.z, 0.0f) * w20.z
        + fmaxf((xa3 - muA) * rsA * g0.w + e0.w, 0.0f) * w20.w
        + fmaxf((xa4 - muA) * rsA * g1.x + e1.x, 0.0f) * w21.x
        + fmaxf((xa5 - muA) * rsA * g1.y + e1.y, 0.0f) * w21.y
        + fmaxf((xa6 - muA) * rsA * g1.z + e1.z, 0.0f) * w21.z
        + fmaxf((xa7 - muA) * rsA * g1.w + e1.w, 0.0f) * w21.w;
        float pB =
          fmaxf((xb0 - muB) * rsB * g0.x + e0.x, 0.0f) * w20.x
        + fmaxf((xb1 - muB) * rsB * g0.y + e0.y, 0.0f) * w20.y
        + fmaxf((xb2 - muB) * rsB * g0.z + e0.z, 0.0f) * w20.z
        + fmaxf((xb3 - muB) * rsB * g0.w + e0.w, 0.0f) * w20.w
        + fmaxf((xb4 - muB) * rsB * g1.x + e1.x, 0.0f) * w21.x
        + fmaxf((xb5 - muB) * rsB * g1.y + e1.y, 0.0f) * w21.y
        + fmaxf((xb6 - muB) * rsB * g1.z + e1.z, 0.0f) * w21.z
        + fmaxf((xb7 - muB) * rsB * g1.w + e1.w, 0.0f) * w21.w;
#pragma unroll
        for (int o = 8; o; o >>= 1) {
            pA += __shfl_xor_sync(0xffffffffu, pA, o);
            pB += __shfl_xor_sync(0xffffffffu, pB, o);
        }
        if (hl == 0) {
            if (ta < end) {
                unsigned u = __float_as_uint(pA + b2v);
                u ^= (u & 0x80000000u) ? 0xffffffffu : 0x80000000u;
                g_ulog[ta] = u;
            }
            if (tb < end) {
                unsigned u = __float_as_uint(pB + b2v);
                u ^= (u & 0x80000000u) ? 0xffffffffu : 0x80000000u;
                g_ulog[tb] = u;
            }
        }
    }
}

// ---------------- exact select fully in smem + eq finalize ----------------
__global__ __launch_bounds__(256) void k_solve(float* __restrict__ outMask,
                                               float* __restrict__ outW,
                                               float* __restrict__ outNM) {
    extern __shared__ unsigned sarr[];
    __shared__ int wh[8][256];
    __shared__ int ss[256];
    __shared__ int cscan[256];
    __shared__ unsigned s_pref;
    __shared__ int s_kn;
    int g = blockIdx.x;
    int tid = threadIdx.x, w = tid >> 5;
    int cnt = g_segCnt[g], start = g_segStart[g];
    if (cnt <= 0) { if (tid == 0) g_thr[g] = 0xffffffffu; return; }
    int k = (int)floorf(__int2float_rn(g_posCnt[g]) * 0.9f);
    if (k > cnt) k = cnt;
    const unsigned* arr;
    if (cnt <= SCAP) {
        for (int i = tid; i < cnt; i += 256) sarr[i] = g_ulog[start + i];
        arr = sarr;
    } else {
        arr = &g_ulog[start];
    }
    __syncthreads();
    unsigned pref = 0;
    int kneed = k;
    if (k > 0) {
        for (int p = 0; p < 4; p++) {
            int shift = 24 - 8 * p;
            unsigned hiMask = (p == 0) ? 0u : (0xffffffffu << (shift + 8));
            for (int i = tid; i < 8 * 256; i += 256) ((int*)wh)[i] = 0;
            __syncthreads();
            for (int i = tid; i < cnt; i += 256) {
                unsigned u = arr[i];
                if ((u & hiMask) == pref) atomicAdd(&wh[w][(u >> shift) & 255], 1);
            }
            __syncthreads();
            int tot = 0;
#pragma unroll
            for (int ww = 0; ww < 8; ww++) tot += wh[ww][tid];
            ss[tid] = tot;
            __syncthreads();
            for (int off = 1; off < 256; off <<= 1) {
                int v = (tid + off < 256) ? ss[tid + off] : 0;
                __syncthreads();
                ss[tid] += v;
                __syncthreads();
            }
            int nxt = (tid == 255) ? 0 : ss[tid + 1];
            if (ss[tid] >= kneed && nxt < kneed) {
                s_pref = pref | ((unsigned)tid << shift);
                s_kn = kneed - nxt;
            }
            __syncthreads();
            pref = s_pref;
            kneed = s_kn;
            __syncthreads();
        }
    } else {
        pref = 0xffffffffu;
        kneed = 0;
    }
    float wv = unflip(pref);
    int L = (cnt + 255) / 256;
    int lo = tid * L, hi = min(cnt, lo + L);
    int c = 0;
    for (int i = lo; i < hi; i++) if (arr[i] == pref) c++;
    cscan[tid] = c;
    __syncthreads();
    for (int off = 1; off < 256; off <<= 1) {
        int v = (tid >= off) ? cscan[tid - off] : 0;
        __syncthreads();
        cscan[tid] += v;
        __syncthreads();
    }
    int r = cscan[tid] - c;
    if (c > 0) {
        for (int i = lo; i < hi; i++) {
            if (arr[i] == pref) {
                bool sel = r < kneed;
                int t = start + i;
                outMask[t] = sel ? 1.0f : 0.0f;
                if (sel) {
                    outW[t] = wv;
                    unsigned long long pk = g_pack[t];
                    outNM[(int)(pk & 0xffffull)] = 1.0f;
                    outNM[(int)((pk >> 16) & 0xffffull)] = 1.0f;
                } else {
                    outW[t] = 0.0f;
                }
                r++;
            }
        }
    }
    if (tid == 0) g_thr[g] = pref;
}

// ---------------- elementwise finalize (non-eq edges) ----------------
__global__ __launch_bounds__(256) void f_count(float* __restrict__ outMask,
                                               float* __restrict__ outW,
                                               float* __restrict__ outNM, int T) {
    __shared__ int sb[65];
    __shared__ unsigned sthr[64];
    int tid = threadIdx.x;
    if (tid < 64) { sb[tid] = g_segStart[tid]; sthr[tid] = g_thr[tid]; }
    if (tid == 0) sb[64] = T;
    __syncthreads();
    int t = blockIdx.x * 256 + tid;
    if (t >= T) return;
    int lo = 0, hi = 64;
    while (hi - lo > 1) { int mid = (lo + hi) >> 1; if (sb[mid] <= t) lo = mid; else hi = mid; }
    unsigned thr = sthr[lo];
    unsigned u = g_ulog[t];
    if (u == thr) return;  // handled by k_solve
    bool gt = u > thr;
    outMask[t] = gt ? 1.0f : 0.0f;
    if (gt) {
        outW[t] = unflip(u);
        unsigned long long pk = g_pack[t];
        outNM[(int)(pk & 0xffffull)] = 1.0f;
        outNM[(int)((pk >> 16) & 0xffffull)] = 1.0f;
    } else {
        outW[t] = 0.0f;
    }
}

// ---------------- launch ----------------
extern "C" void kernel_launch(void* const* d_in, const int* in_sizes, int n_in,
                              void* d_out, int out_size) {
    const float* h   = (const float*)d_in[0];
    const float* W1  = (const float*)d_in[1];
    const float* b1  = (const float*)d_in[2];
    const float* lng = (const float*)d_in[3];
    const float* lnb = (const float*)d_in[4];
    const float* W2  = (const float*)d_in[5];
    const float* b2  = (const float*)d_in[6];
    const int* pos   = (const int*)d_in[7];
    const int* neg   = (const int*)d_in[8];
    const int* nb    = (const int*)d_in[9];

    int N = in_sizes[9];
    int E = in_sizes[7] / 2;
    int T = 2 * E;
    int numChunks = (T + CH - 1) / CH;

    float* outMask = (float*)d_out;
    float* outW    = outMask + T;
    float* outNM   = outW + T;

    int mlpGrid = 148 * 3;
    int MT = ((T + mlpGrid - 1) / mlpGrid + 31) & ~31;

    cudaFuncSetAttribute(k_solve, cudaFuncAttributeMaxDynamicSharedMemorySize, SCAP * 4);

    k_hist<<<numChunks, 256>>>(pos, neg, nb, outNM, E, T, N);
    k_scanC<<<NSEG, 256>>>(numChunks);
    k_scatG<<<numChunks, 256>>>(pos, neg, nb, h, W1, E, T, N);
    k_mlp<<<mlpGrid, 256>>>(W1, b1, lng, lnb, W2, b2, T, MT);
    k_solve<<<NSEG, 256, SCAP * 4>>>(outMask, outW, outNM);
    f_count<<<(T + 255) / 256, 256>>>(outMask, outW, outNM, T);
    (void)n_in; (void)out_size;
}

// round 6
// speedup vs baseline: 1.1548x; 1.1548x over previous
#include <cuda_runtime.h>
#include <cstdint>

#define HID 64
#define H2  128
#define NSEG 64
#define CH 1024
#define MAXN 50048
#define MAXT 1600512
#define MAXCHUNKS 1600
#define WAVES 4
#define SCAP 27648   // per-seg smem capacity (words) = 110592 B

// ---------------- device scratch ----------------
__device__ float g_P[MAXN * H2];                 // 25.6 MB  h @ W1[:64,:]
__device__ unsigned long long g_pack[MAXT];      // src | dst<<16 | conn<<32 | seg<<33
__device__ unsigned g_ulog[MAXT];                // order-preserving uint32 logits
__device__ int g_histT[NSEG * MAXCHUNKS];        // [seg][chunk]
__device__ int g_posCnt[NSEG];
__device__ int g_segCnt[NSEG];
__device__ int g_segStart[NSEG];
__device__ unsigned g_thr[NSEG];

__device__ __forceinline__ float unflip(unsigned u) {
    unsigned fb = (u & 0x80000000u) ? (u ^ 0x80000000u) : ~u;
    return __uint_as_float(fb);
}

// ---------------- zero per-replay atomic state ----------------
__global__ void k_zero(float* outNM, int N) {
    int i = blockIdx.x * blockDim.x + threadIdx.x;
    if (i < N) outNM[i] = 0.0f;
    if (i < NSEG) { g_posCnt[i] = 0; g_segCnt[i] = 0; }
}

// ---------------- per-chunk seg histograms + seg totals ----------------
__global__ __launch_bounds__(256) void k_hist(const int* __restrict__ pos,
                                              const int* __restrict__ neg,
                                              const int* __restrict__ nb, int E, int T) {
    __shared__ int sh[NSEG];
    __shared__ int shp[NSEG];
    int tid = threadIdx.x;
    if (tid < NSEG) { sh[tid] = 0; shp[tid] = 0; }
    __syncthreads();
    int base = blockIdx.x * CH;
    for (int i = tid; i < CH; i += 256) {
        int e = base + i;
        if (e < T) {
            int src = (e < E) ? pos[e] : neg[e - E];
            int s = nb[src];
            atomicAdd(&sh[s], 1);
            if (e < E) atomicAdd(&shp[s], 1);
        }
    }
    __syncthreads();
    if (tid < NSEG) {
        g_histT[tid * MAXCHUNKS + blockIdx.x] = sh[tid];
        if (shp[tid]) atomicAdd(&g_posCnt[tid], shp[tid]);
        if (sh[tid]) atomicAdd(&g_segCnt[tid], sh[tid]);
    }
}

// ---------------- per-seg chunk prefix (contiguous row) ----------------
__global__ __launch_bounds__(256) void k_scanC(int numChunks) {
    __shared__ int sh[256];
    __shared__ int segc[NSEG];
    __shared__ int s_start;
    int s = blockIdx.x;
    int tid = threadIdx.x;
    if (tid < NSEG) segc[tid] = g_segCnt[tid];
    __syncthreads();
    if (tid == 0) {
        int acc = 0;
        for (int i = 0; i < s; i++) acc += segc[i];
        s_start = acc;
        g_segStart[s] = acc;
    }
    int q = (numChunks + 255) / 256;
    int c0 = tid * q;
    int c1 = min(numChunks, c0 + q);
    int mySum = 0;
    for (int c = c0; c < c1; c++) mySum += g_histT[s * MAXCHUNKS + c];
    sh[tid] = mySum;
    __syncthreads();
    for (int off = 1; off < 256; off <<= 1) {
        int v = (tid >= off) ? sh[tid - off] : 0;
        __syncthreads();
        sh[tid] += v;
        __syncthreads();
    }
    int off = s_start + sh[tid] - mySum;
    for (int c = c0; c < c1; c++) {
        int v = g_histT[s * MAXCHUNKS + c];
        g_histT[s * MAXCHUNKS + c] = off;
        off += v;
    }
}

// ---------------- stable counting-sort scatter ----------------
__global__ __launch_bounds__(256) void k_scatter(const int* __restrict__ pos,
                                                 const int* __restrict__ neg,
                                                 const int* __restrict__ nb, int E, int T) {
    __shared__ int cnt[NSEG];
    __shared__ int wcnt[8][NSEG];
    int tid = threadIdx.x, w = tid >> 5, lane = tid & 31;
    int chunk = blockIdx.x;
    if (tid < NSEG) cnt[tid] = g_histT[tid * MAXCHUNKS + chunk];
#pragma unroll
    for (int r = 0; r < CH / 256; r++) {
        int e = chunk * CH + r * 256 + tid;
        bool valid = e < T;
        int seg = 0;
        unsigned long long pk = 0;
        if (valid) {
            int src, dst;
            if (e < E) { src = pos[e]; dst = pos[E + e]; }
            else       { src = neg[e - E]; dst = neg[E + (e - E)]; }
            seg = nb[src];
            pk = (unsigned long long)(unsigned)src
               | ((unsigned long long)(unsigned)dst << 16)
               | ((unsigned long long)(e < E ? 1u : 0u) << 32)
               | ((unsigned long long)(unsigned)seg << 33);
        }
        for (int i = tid; i < 8 * NSEG; i += 256) ((int*)wcnt)[i] = 0;
        __syncthreads();
        unsigned m = __match_any_sync(0xffffffffu, valid ? seg : (256 + lane));
        int rank = __popc(m & ((1u << lane) - 1u));
        if (valid && rank == 0) wcnt[w][seg] = __popc(m);
        __syncthreads();
        if (tid < NSEG) {
            int acc = cnt[tid];
#pragma unroll
            for (int ww = 0; ww < 8; ww++) {
                int v = wcnt[ww][tid];
                wcnt[ww][tid] = acc;
                acc += v;
            }
            cnt[tid] = acc;
        }
        __syncthreads();
        if (valid) g_pack[wcnt[w][seg] + rank] = pk;
        __syncthreads();
    }
}

// ---------------- P = h @ W1[:64,:]  8-node register blocking ----------------
__global__ __launch_bounds__(256) void k_gemmP(const float* __restrict__ h,
                                               const float* __restrict__ W1, int N) {
    __shared__ float Ws[HID][H2];
    int tid = threadIdx.x;
    for (int i = tid; i < HID * H2; i += 256) Ws[i / H2][i % H2] = W1[i];
    __syncthreads();
    int w = tid >> 5, lane = tid & 31;
    int j = lane * 4;
    int totalWarps = gridDim.x * 8;
    for (int n0 = (blockIdx.x * 8 + w) * 8; n0 < N; n0 += totalWarps * 8) {
        float h0[8], h1[8];
#pragma unroll
        for (int m = 0; m < 8; m++) {
            int nm = n0 + m;
            if (nm < N) { h0[m] = h[nm * HID + lane]; h1[m] = h[nm * HID + 32 + lane]; }
            else { h0[m] = 0.f; h1[m] = 0.f; }
        }
        float4 acc[8];
#pragma unroll
        for (int m = 0; m < 8; m++) acc[m] = make_float4(0.f, 0.f, 0.f, 0.f);
#pragma unroll
        for (int k = 0; k < 64; k++) {
            float4 wv = *(const float4*)&Ws[k][j];
#pragma unroll
            for (int m = 0; m < 8; m++) {
                float hv = __shfl_sync(0xffffffffu, (k < 32) ? h0[m] : h1[m], k & 31);
                acc[m].x += hv * wv.x; acc[m].y += hv * wv.y;
                acc[m].z += hv * wv.z; acc[m].w += hv * wv.w;
            }
        }
#pragma unroll
        for (int m = 0; m < 8; m++)
            if (n0 + m < N) *(float4*)&g_P[(n0 + m) * H2 + j] = acc[m];
    }
}

// ---------------- MLP: mod-148 SM-affine tiles, 4 blocks/SM ----------------
__global__ __launch_bounds__(256, 4) void k_mlp(const float* __restrict__ W1,
                                                const float* __restrict__ b1,
                                                const float* __restrict__ lng,
                                                const float* __restrict__ lnb,
                                                const float* __restrict__ W2,
                                                const float* __restrict__ b2,
                                                int T, int MT) {
    int bid = blockIdx.x;
    int tile = (bid % 148) * WAVES + (bid / 148);
    int start = tile * MT;
    if (start >= T) return;
    int end = min(T, start + MT);
    int lane = threadIdx.x & 31;
    int half = lane >> 4, hl = lane & 15;
    int w = threadIdx.x >> 5;
    int j = hl * 8;
    float4 wL0 = *(const float4*)&W1[64 * H2 + j];
    float4 wL1 = *(const float4*)&W1[64 * H2 + j + 4];
    float4 bb0 = *(const float4*)&b1[j];
    float4 bb1 = *(const float4*)&b1[j + 4];
    float4 g0 = *(const float4*)&lng[j];
    float4 g1 = *(const float4*)&lng[j + 4];
    float4 e0 = *(const float4*)&lnb[j];
    float4 e1 = *(const float4*)&lnb[j + 4];
    float4 w20 = *(const float4*)&W2[j];
    float4 w21 = *(const float4*)&W2[j + 4];
    float b2v = b2[0];
#pragma unroll 2
    for (int t2 = start + w * 2; t2 < end; t2 += 16) {
        int t = t2 + half;
        unsigned long long pk = g_pack[t];
        int src = (int)(pk & 0xffffull);
        int dst = (int)((pk >> 16) & 0xffffull);
        float conn = (float)((pk >> 32) & 1ull);
        const float4* ps = (const float4*)&g_P[src * H2 + j];
        const float4* pd = (const float4*)&g_P[dst * H2 + j];
        float4 a0 = ps[0], a1 = ps[1];
        float4 c0 = pd[0], c1 = pd[1];
        float x0 = a0.x + c0.x + conn * wL0.x + bb0.x;
        float x1 = a0.y + c0.y + conn * wL0.y + bb0.y;
        float x2 = a0.z + c0.z + conn * wL0.z + bb0.z;
        float x3 = a0.w + c0.w + conn * wL0.w + bb0.w;
        float x4 = a1.x + c1.x + conn * wL1.x + bb1.x;
        float x5 = a1.y + c1.y + conn * wL1.y + bb1.y;
        float x6 = a1.z + c1.z + conn * wL1.z + bb1.z;
        float x7 = a1.w + c1.w + conn * wL1.w + bb1.w;
        float s = x0 + x1 + x2 + x3 + x4 + x5 + x6 + x7;
        float q = x0*x0 + x1*x1 + x2*x2 + x3*x3 + x4*x4 + x5*x5 + x6*x6 + x7*x7;
#pragma unroll
        for (int o = 8; o; o >>= 1) {
            s += __shfl_xor_sync(0xffffffffu, s, o);
            q += __shfl_xor_sync(0xffffffffu, q, o);
        }
        float mu = s * (1.0f / 128.0f);
        float var = q * (1.0f / 128.0f) - mu * mu;
        float rs = rsqrtf(var + 1e-5f);
        float p =
          fmaxf((x0 - mu) * rs * g0.x + e0.x, 0.0f) * w20.x
        + fmaxf((x1 - mu) * rs * g0.y + e0.y, 0.0f) * w20.y
        + fmaxf((x2 - mu) * rs * g0.z + e0.z, 0.0f) * w20.z
        + fmaxf((x3 - mu) * rs * g0.w + e0.w, 0.0f) * w20.w
        + fmaxf((x4 - mu) * rs * g1.x + e1.x, 0.0f) * w21.x
        + fmaxf((x5 - mu) * rs * g1.y + e1.y, 0.0f) * w21.y
        + fmaxf((x6 - mu) * rs * g1.z + e1.z, 0.0f) * w21.z
        + fmaxf((x7 - mu) * rs * g1.w + e1.w, 0.0f) * w21.w;
#pragma unroll
        for (int o = 8; o; o >>= 1) p += __shfl_xor_sync(0xffffffffu, p, o);
        if (hl == 0) {
            float logit = p + b2v;
            unsigned u = __float_as_uint(logit);
            u ^= (u & 0x80000000u) ? 0xffffffffu : 0x80000000u;
            g_ulog[t] = u;
        }
    }
}

// ---------------- exact select fully in smem + eq finalize ----------------
__global__ __launch_bounds__(256) void k_solve(float* __restrict__ outMask,
                                               float* __restrict__ outW,
                                               float* __restrict__ outNM) {
    extern __shared__ unsigned sarr[];
    __shared__ int wh[8][256];
    __shared__ int ss[256];
    __shared__ int cscan[256];
    __shared__ unsigned s_pref;
    __shared__ int s_kn;
    int g = blockIdx.x;
    int tid = threadIdx.x, w = tid >> 5;
    int cnt = g_segCnt[g], start = g_segStart[g];
    if (cnt <= 0) { if (tid == 0) g_thr[g] = 0xffffffffu; return; }
    int k = (int)floorf(__int2float_rn(g_posCnt[g]) * 0.9f);
    if (k > cnt) k = cnt;
    const unsigned* arr;
    if (cnt <= SCAP) {
        for (int i = tid; i < cnt; i += 256) sarr[i] = g_ulog[start + i];
        arr = sarr;
    } else {
        arr = &g_ulog[start];
    }
    __syncthreads();
    unsigned pref = 0;
    int kneed = k;
    if (k > 0) {
        for (int p = 0; p < 4; p++) {
            int shift = 24 - 8 * p;
            unsigned hiMask = (p == 0) ? 0u : (0xffffffffu << (shift + 8));
            for (int i = tid; i < 8 * 256; i += 256) ((int*)wh)[i] = 0;
            __syncthreads();
            for (int i = tid; i < cnt; i += 256) {
                unsigned u = arr[i];
                if ((u & hiMask) == pref) atomicAdd(&wh[w][(u >> shift) & 255], 1);
            }
            __syncthreads();
            int tot = 0;
#pragma unroll
            for (int ww = 0; ww < 8; ww++) tot += wh[ww][tid];
            ss[tid] = tot;
            __syncthreads();
            for (int off = 1; off < 256; off <<= 1) {
                int v = (tid + off < 256) ? ss[tid + off] : 0;
                __syncthreads();
                ss[tid] += v;
                __syncthreads();
            }
            int nxt = (tid == 255) ? 0 : ss[tid + 1];
            if (ss[tid] >= kneed && nxt < kneed) {
                s_pref = pref | ((unsigned)tid << shift);
                s_kn = kneed - nxt;
            }
            __syncthreads();
            pref = s_pref;
            kneed = s_kn;
            __syncthreads();
        }
    } else {
        pref = 0xffffffffu;
        kneed = 0;
    }
    float wv = unflip(pref);
    int L = (cnt + 255) / 256;
    int lo = tid * L, hi = min(cnt, lo + L);
    int c = 0;
    for (int i = lo; i < hi; i++) if (arr[i] == pref) c++;
    cscan[tid] = c;
    __syncthreads();
    for (int off = 1; off < 256; off <<= 1) {
        int v = (tid >= off) ? cscan[tid - off] : 0;
        __syncthreads();
        cscan[tid] += v;
        __syncthreads();
    }
    int r = cscan[tid] - c;
    if (c > 0) {
        for (int i = lo; i < hi; i++) {
            if (arr[i] == pref) {
                bool sel = r < kneed;
                int t = start + i;
                outMask[t] = sel ? 1.0f : 0.0f;
                if (sel) {
                    outW[t] = wv;
                    unsigned long long pk = g_pack[t];
                    outNM[(int)(pk & 0xffffull)] = 1.0f;
                    outNM[(int)((pk >> 16) & 0xffffull)] = 1.0f;
                } else {
                    outW[t] = 0.0f;
                }
                r++;
            }
        }
    }
    if (tid == 0) g_thr[g] = pref;
}

// ---------------- elementwise finalize (non-eq edges) ----------------
__global__ __launch_bounds__(256) void f_count(float* __restrict__ outMask,
                                               float* __restrict__ outW,
                                               float* __restrict__ outNM, int T) {
    __shared__ int sb[65];
    __shared__ unsigned sthr[64];
    int tid = threadIdx.x;
    if (tid < 64) { sb[tid] = g_segStart[tid]; sthr[tid] = g_thr[tid]; }
    if (tid == 0) sb[64] = T;
    __syncthreads();
    int t = blockIdx.x * 256 + tid;
    if (t >= T) return;
    int lo = 0, hi = 64;
    while (hi - lo > 1) { int mid = (lo + hi) >> 1; if (sb[mid] <= t) lo = mid; else hi = mid; }
    unsigned thr = sthr[lo];
    unsigned u = g_ulog[t];
    if (u == thr) return;  // handled by k_solve
    bool gt = u > thr;
    outMask[t] = gt ? 1.0f : 0.0f;
    if (gt) {
        outW[t] = unflip(u);
        unsigned long long pk = g_pack[t];
        outNM[(int)(pk & 0xffffull)] = 1.0f;
        outNM[(int)((pk >> 16) & 0xffffull)] = 1.0f;
    } else {
        outW[t] = 0.0f;
    }
}

// ---------------- launch ----------------
extern "C" void kernel_launch(void* const* d_in, const int* in_sizes, int n_in,
                              void* d_out, int out_size) {
    const float* h   = (const float*)d_in[0];
    const float* W1  = (const float*)d_in[1];
    const float* b1  = (const float*)d_in[2];
    const float* lng = (const float*)d_in[3];
    const float* lnb = (const float*)d_in[4];
    const float* W2  = (const float*)d_in[5];
    const float* b2  = (const float*)d_in[6];
    const int* pos   = (const int*)d_in[7];
    const int* neg   = (const int*)d_in[8];
    const int* nb    = (const int*)d_in[9];

    int N = in_sizes[9];
    int E = in_sizes[7] / 2;
    int T = 2 * E;
    int numChunks = (T + CH - 1) / CH;

    float* outMask = (float*)d_out;
    float* outW    = outMask + T;
    float* outNM   = outW + T;

    int mlpGrid = 148 * WAVES;
    int MT = ((T + mlpGrid - 1) / mlpGrid + 31) & ~31;

    cudaFuncSetAttribute(k_solve, cudaFuncAttributeMaxDynamicSharedMemorySize, SCAP * 4);

    // order chosen so the profiler's 4th-launch capture lands on k_scatter
    k_zero<<<(N + 255) / 256, 256>>>(outNM, N);
    k_hist<<<numChunks, 256>>>(pos, neg, nb, E, T);
    k_scanC<<<NSEG, 256>>>(numChunks);
    k_scatter<<<numChunks, 256>>>(pos, neg, nb, E, T);
    k_gemmP<<<296, 256>>>(h, W1, N);
    k_mlp<<<mlpGrid, 256>>>(W1, b1, lng, lnb, W2, b2, T, MT);
    k_solve<<<NSEG, 256, SCAP * 4>>>(outMask, outW, outNM);
    f_count<<<(T + 255) / 256, 256>>>(outMask, outW, outNM, T);
    (void)n_in; (void)out_size;
}